// round 4
// baseline (speedup 1.0000x reference)
#include <cuda_runtime.h>

// NormmaxBisect, alpha=1.5, d=2048: p = clamp(x - tau, 0)^2 / sum(...),
// tau solves sum(clamp(x - tau, 0)^3) = 1.
//
// Active-set kernel: tau >= max-1 always, so only elements x > max-1 ever
// contribute to the solver sums. One warp per row:
//   1) load row into registers, warp-max
//   2) compact actives (x > max-1) into a per-warp smem buffer (2-scan + prefix)
//   3) 12 bisection + 3 Newton passes over the tiny active set (fp32-exact tau)
//   4) one full-row pass: p = clamp(x-tau)^2 * (1/sum), streamed out
// Fallback (cnt > CAP, statistically impossible here): solve over full register row.

#define D 2048
#define WPB 8
#define THREADS (WPB * 32)
#define CAP 1024                 // per-warp active buffer; 8*1024*4 = 32KB static smem
#define N_BISECT 12
#define N_NEWTON 3
#define DM0 0.9779029130879204f  // 1 - (1/2048)^0.5

static __device__ __forceinline__ float warp_sum(float v) {
    #pragma unroll
    for (int o = 16; o; o >>= 1) v += __shfl_xor_sync(0xffffffffu, v, o);
    return v;
}
static __device__ __forceinline__ float warp_max(float v) {
    #pragma unroll
    for (int o = 16; o; o >>= 1) v = fmaxf(v, __shfl_xor_sync(0xffffffffu, v, o));
    return v;
}

// --- sums over compacted smem actives ---
static __device__ __forceinline__ float s3_smem(const float* sbuf, int nv, int lane, float tau) {
    float s3 = 0.0f;
    for (int i = 0; i < nv; ++i) {
        float c = fmaxf(sbuf[i * 32 + lane] - tau, 0.0f);
        s3 = fmaf(c * c, c, s3);
    }
    return warp_sum(s3);
}
static __device__ __forceinline__ void s23_smem(const float* sbuf, int nv, int lane, float tau,
                                                float& s2o, float& s3o) {
    float s2 = 0.0f, s3 = 0.0f;
    for (int i = 0; i < nv; ++i) {
        float c = fmaxf(sbuf[i * 32 + lane] - tau, 0.0f);
        float c2 = c * c;
        s2 += c2;
        s3 = fmaf(c2, c, s3);
    }
    s2o = warp_sum(s2);
    s3o = warp_sum(s3);
}

// --- sums over the full register-resident row (fallback path) ---
static __device__ __forceinline__ float s3_regs(const float4* v, float tau) {
    float s3 = 0.0f;
    #pragma unroll
    for (int j = 0; j < 16; ++j) {
        float cx = fmaxf(v[j].x - tau, 0.0f);
        float cy = fmaxf(v[j].y - tau, 0.0f);
        float cz = fmaxf(v[j].z - tau, 0.0f);
        float cw = fmaxf(v[j].w - tau, 0.0f);
        s3 = fmaf(cx * cx, cx, s3);
        s3 = fmaf(cy * cy, cy, s3);
        s3 = fmaf(cz * cz, cz, s3);
        s3 = fmaf(cw * cw, cw, s3);
    }
    return warp_sum(s3);
}
static __device__ __forceinline__ void s23_regs(const float4* v, float tau, float& s2o, float& s3o) {
    float s2 = 0.0f, s3 = 0.0f;
    #pragma unroll
    for (int j = 0; j < 16; ++j) {
        float cx = fmaxf(v[j].x - tau, 0.0f);
        float cy = fmaxf(v[j].y - tau, 0.0f);
        float cz = fmaxf(v[j].z - tau, 0.0f);
        float cw = fmaxf(v[j].w - tau, 0.0f);
        float c2x = cx * cx, c2y = cy * cy, c2z = cz * cz, c2w = cw * cw;
        s2 += c2x + c2y + c2z + c2w;
        s3 = fmaf(c2x, cx, s3);
        s3 = fmaf(c2y, cy, s3);
        s3 = fmaf(c2z, cz, s3);
        s3 = fmaf(c2w, cw, s3);
    }
    s2o = warp_sum(s2);
    s3o = warp_sum(s3);
}

__global__ __launch_bounds__(THREADS, 2)
void normmax_active_kernel(const float* __restrict__ X, float* __restrict__ O, int nrows) {
    __shared__ float sbuf_all[WPB * CAP];
    const int warp = blockIdx.x * WPB + (threadIdx.x >> 5);
    if (warp >= nrows) return;
    const int lane = threadIdx.x & 31;
    float* sbuf = sbuf_all + (threadIdx.x >> 5) * CAP;

    const float4* __restrict__ src = reinterpret_cast<const float4*>(X + (size_t)warp * D);

    // ---- load row (coalesced) + warp max ----
    float4 v[16];
    float mx = -3.4e38f;
    #pragma unroll
    for (int j = 0; j < 16; ++j) {
        float4 t = src[j * 32 + lane];
        v[j] = t;
        mx = fmaxf(mx, fmaxf(fmaxf(t.x, t.y), fmaxf(t.z, t.w)));
    }
    mx = warp_max(mx);
    const float thr = mx - 1.0f;   // = tau_lo; only x > thr can ever contribute

    // ---- scan 1: count actives per lane ----
    int cnt = 0;
    #pragma unroll
    for (int j = 0; j < 16; ++j) {
        cnt += (v[j].x > thr) + (v[j].y > thr) + (v[j].z > thr) + (v[j].w > thr);
    }
    // inclusive warp prefix sum
    int pre = cnt;
    #pragma unroll
    for (int o = 1; o < 32; o <<= 1) {
        int t = __shfl_up_sync(0xffffffffu, pre, o);
        if (lane >= o) pre += t;
    }
    const int total = __shfl_sync(0xffffffffu, pre, 31);

    float tau;
    int nv = 0;
    if (total <= CAP) {
        // ---- scan 2: compact actives into smem ----
        int k = pre - cnt;  // exclusive base
        #pragma unroll
        for (int j = 0; j < 16; ++j) {
            if (v[j].x > thr) sbuf[k++] = v[j].x;
            if (v[j].y > thr) sbuf[k++] = v[j].y;
            if (v[j].z > thr) sbuf[k++] = v[j].z;
            if (v[j].w > thr) sbuf[k++] = v[j].w;
        }
        nv = (total + 31) >> 5;
        // pad last chunk so every lane reads a harmless value
        for (int i = total + lane; i < nv * 32; i += 32) sbuf[i] = -1e30f;
        __syncwarp();

        // ---- bisection on actives ----
        float tau_lo = thr;
        float dm = DM0;
        #pragma unroll
        for (int it = 0; it < N_BISECT; ++it) {
            dm *= 0.5f;
            const float tm = tau_lo + dm;
            if (s3_smem(sbuf, nv, lane, tm) >= 1.0f) tau_lo = tm;  // warp-uniform
        }
        // ---- Newton (convex f, from f>=0 side: monotone, no overshoot) ----
        tau = tau_lo;
        #pragma unroll
        for (int it = 0; it < N_NEWTON; ++it) {
            float s2, s3;
            s23_smem(sbuf, nv, lane, tau, s2, s3);
            tau += __fdividef(s3 - 1.0f, 3.0f * s2);
        }
    } else {
        // ---- fallback: solve over the full register row (never taken for this input) ----
        float tau_lo = thr;
        float dm = DM0;
        for (int it = 0; it < N_BISECT + 8; ++it) {   // extra bisections for safety
            dm *= 0.5f;
            const float tm = tau_lo + dm;
            if (s3_regs(v, tm) >= 1.0f) tau_lo = tm;
        }
        tau = tau_lo;
        for (int it = 0; it < N_NEWTON; ++it) {
            float s2, s3;
            s23_regs(v, tau, s2, s3);
            tau += __fdividef(s3 - 1.0f, 3.0f * s2);
        }
    }

    // ---- normalization constant: sum(c^2) at final tau ----
    float s2;
    if (total <= CAP) {
        float acc = 0.0f;
        for (int i = 0; i < nv; ++i) {
            float c = fmaxf(sbuf[i * 32 + lane] - tau, 0.0f);
            acc = fmaf(c, c, acc);
        }
        s2 = warp_sum(acc);
    } else {
        float dummy;
        s23_regs(v, tau, s2, dummy);
    }
    const float inv = __fdividef(1.0f, s2);

    // ---- final pass: p = clamp(x - tau)^2 * inv, streamed out ----
    float4* __restrict__ dst = reinterpret_cast<float4*>(O + (size_t)warp * D);
    #pragma unroll
    for (int j = 0; j < 16; ++j) {
        float cx = fmaxf(v[j].x - tau, 0.0f);
        float cy = fmaxf(v[j].y - tau, 0.0f);
        float cz = fmaxf(v[j].z - tau, 0.0f);
        float cw = fmaxf(v[j].w - tau, 0.0f);
        float4 p;
        p.x = cx * cx * inv;
        p.y = cy * cy * inv;
        p.z = cz * cz * inv;
        p.w = cw * cw * inv;
        dst[j * 32 + lane] = p;
    }
}

extern "C" void kernel_launch(void* const* d_in, const int* in_sizes, int n_in,
                              void* d_out, int out_size) {
    const float* X = (const float*)d_in[0];
    float* O = (float*)d_out;
    const int nrows = in_sizes[0] / D;                 // 65536
    const int grid = (nrows + WPB - 1) / WPB;
    normmax_active_kernel<<<grid, THREADS>>>(X, O, nrows);
}

// round 5
// speedup vs baseline: 1.0039x; 1.0039x over previous
#include <cuda_runtime.h>

// NormmaxBisect, alpha=1.5, d=2048: p = clamp(x - tau, 0)^2 / sum(...),
// tau solves sum(clamp(x - tau, 0)^3) = 1.
//
// Active-set kernel: tau >= max-1 always, so only elements x > max-1 ever
// contribute to the solver sums. One warp per row:
//   1) load row into registers, warp-max
//   2) compact actives (x > max-1) into a per-warp smem buffer (2-scan + prefix)
//   3) 12 bisection + 3 Newton passes over the tiny active set (fp32-exact tau)
//   4) one full-row pass: p = clamp(x-tau)^2 * (1/sum), streamed out
// Fallback (cnt > CAP, statistically impossible here): solve over full register row.

#define D 2048
#define WPB 8
#define THREADS (WPB * 32)
#define CAP 1024                 // per-warp active buffer; 8*1024*4 = 32KB static smem
#define N_BISECT 12
#define N_NEWTON 3
#define DM0 0.9779029130879204f  // 1 - (1/2048)^0.5

static __device__ __forceinline__ float warp_sum(float v) {
    #pragma unroll
    for (int o = 16; o; o >>= 1) v += __shfl_xor_sync(0xffffffffu, v, o);
    return v;
}
static __device__ __forceinline__ float warp_max(float v) {
    #pragma unroll
    for (int o = 16; o; o >>= 1) v = fmaxf(v, __shfl_xor_sync(0xffffffffu, v, o));
    return v;
}

// --- sums over compacted smem actives ---
static __device__ __forceinline__ float s3_smem(const float* sbuf, int nv, int lane, float tau) {
    float s3 = 0.0f;
    for (int i = 0; i < nv; ++i) {
        float c = fmaxf(sbuf[i * 32 + lane] - tau, 0.0f);
        s3 = fmaf(c * c, c, s3);
    }
    return warp_sum(s3);
}
static __device__ __forceinline__ void s23_smem(const float* sbuf, int nv, int lane, float tau,
                                                float& s2o, float& s3o) {
    float s2 = 0.0f, s3 = 0.0f;
    for (int i = 0; i < nv; ++i) {
        float c = fmaxf(sbuf[i * 32 + lane] - tau, 0.0f);
        float c2 = c * c;
        s2 += c2;
        s3 = fmaf(c2, c, s3);
    }
    s2o = warp_sum(s2);
    s3o = warp_sum(s3);
}

// --- sums over the full register-resident row (fallback path) ---
static __device__ __forceinline__ float s3_regs(const float4* v, float tau) {
    float s3 = 0.0f;
    #pragma unroll
    for (int j = 0; j < 16; ++j) {
        float cx = fmaxf(v[j].x - tau, 0.0f);
        float cy = fmaxf(v[j].y - tau, 0.0f);
        float cz = fmaxf(v[j].z - tau, 0.0f);
        float cw = fmaxf(v[j].w - tau, 0.0f);
        s3 = fmaf(cx * cx, cx, s3);
        s3 = fmaf(cy * cy, cy, s3);
        s3 = fmaf(cz * cz, cz, s3);
        s3 = fmaf(cw * cw, cw, s3);
    }
    return warp_sum(s3);
}
static __device__ __forceinline__ void s23_regs(const float4* v, float tau, float& s2o, float& s3o) {
    float s2 = 0.0f, s3 = 0.0f;
    #pragma unroll
    for (int j = 0; j < 16; ++j) {
        float cx = fmaxf(v[j].x - tau, 0.0f);
        float cy = fmaxf(v[j].y - tau, 0.0f);
        float cz = fmaxf(v[j].z - tau, 0.0f);
        float cw = fmaxf(v[j].w - tau, 0.0f);
        float c2x = cx * cx, c2y = cy * cy, c2z = cz * cz, c2w = cw * cw;
        s2 += c2x + c2y + c2z + c2w;
        s3 = fmaf(c2x, cx, s3);
        s3 = fmaf(c2y, cy, s3);
        s3 = fmaf(c2z, cz, s3);
        s3 = fmaf(c2w, cw, s3);
    }
    s2o = warp_sum(s2);
    s3o = warp_sum(s3);
}

__global__ __launch_bounds__(THREADS, 2)
void normmax_active_kernel(const float* __restrict__ X, float* __restrict__ O, int nrows) {
    __shared__ float sbuf_all[WPB * CAP];
    const int warp = blockIdx.x * WPB + (threadIdx.x >> 5);
    if (warp >= nrows) return;
    const int lane = threadIdx.x & 31;
    float* sbuf = sbuf_all + (threadIdx.x >> 5) * CAP;

    const float4* __restrict__ src = reinterpret_cast<const float4*>(X + (size_t)warp * D);

    // ---- load row (coalesced) + warp max ----
    float4 v[16];
    float mx = -3.4e38f;
    #pragma unroll
    for (int j = 0; j < 16; ++j) {
        float4 t = src[j * 32 + lane];
        v[j] = t;
        mx = fmaxf(mx, fmaxf(fmaxf(t.x, t.y), fmaxf(t.z, t.w)));
    }
    mx = warp_max(mx);
    const float thr = mx - 1.0f;   // = tau_lo; only x > thr can ever contribute

    // ---- scan 1: count actives per lane ----
    int cnt = 0;
    #pragma unroll
    for (int j = 0; j < 16; ++j) {
        cnt += (v[j].x > thr) + (v[j].y > thr) + (v[j].z > thr) + (v[j].w > thr);
    }
    // inclusive warp prefix sum
    int pre = cnt;
    #pragma unroll
    for (int o = 1; o < 32; o <<= 1) {
        int t = __shfl_up_sync(0xffffffffu, pre, o);
        if (lane >= o) pre += t;
    }
    const int total = __shfl_sync(0xffffffffu, pre, 31);

    float tau;
    int nv = 0;
    if (total <= CAP) {
        // ---- scan 2: compact actives into smem ----
        int k = pre - cnt;  // exclusive base
        #pragma unroll
        for (int j = 0; j < 16; ++j) {
            if (v[j].x > thr) sbuf[k++] = v[j].x;
            if (v[j].y > thr) sbuf[k++] = v[j].y;
            if (v[j].z > thr) sbuf[k++] = v[j].z;
            if (v[j].w > thr) sbuf[k++] = v[j].w;
        }
        nv = (total + 31) >> 5;
        // pad last chunk so every lane reads a harmless value
        for (int i = total + lane; i < nv * 32; i += 32) sbuf[i] = -1e30f;
        __syncwarp();

        // ---- bisection on actives ----
        float tau_lo = thr;
        float dm = DM0;
        #pragma unroll
        for (int it = 0; it < N_BISECT; ++it) {
            dm *= 0.5f;
            const float tm = tau_lo + dm;
            if (s3_smem(sbuf, nv, lane, tm) >= 1.0f) tau_lo = tm;  // warp-uniform
        }
        // ---- Newton (convex f, from f>=0 side: monotone, no overshoot) ----
        tau = tau_lo;
        #pragma unroll
        for (int it = 0; it < N_NEWTON; ++it) {
            float s2, s3;
            s23_smem(sbuf, nv, lane, tau, s2, s3);
            tau += __fdividef(s3 - 1.0f, 3.0f * s2);
        }
    } else {
        // ---- fallback: solve over the full register row (never taken for this input) ----
        float tau_lo = thr;
        float dm = DM0;
        for (int it = 0; it < N_BISECT + 8; ++it) {   // extra bisections for safety
            dm *= 0.5f;
            const float tm = tau_lo + dm;
            if (s3_regs(v, tm) >= 1.0f) tau_lo = tm;
        }
        tau = tau_lo;
        for (int it = 0; it < N_NEWTON; ++it) {
            float s2, s3;
            s23_regs(v, tau, s2, s3);
            tau += __fdividef(s3 - 1.0f, 3.0f * s2);
        }
    }

    // ---- normalization constant: sum(c^2) at final tau ----
    float s2;
    if (total <= CAP) {
        float acc = 0.0f;
        for (int i = 0; i < nv; ++i) {
            float c = fmaxf(sbuf[i * 32 + lane] - tau, 0.0f);
            acc = fmaf(c, c, acc);
        }
        s2 = warp_sum(acc);
    } else {
        float dummy;
        s23_regs(v, tau, s2, dummy);
    }
    const float inv = __fdividef(1.0f, s2);

    // ---- final pass: p = clamp(x - tau)^2 * inv, streamed out ----
    float4* __restrict__ dst = reinterpret_cast<float4*>(O + (size_t)warp * D);
    #pragma unroll
    for (int j = 0; j < 16; ++j) {
        float cx = fmaxf(v[j].x - tau, 0.0f);
        float cy = fmaxf(v[j].y - tau, 0.0f);
        float cz = fmaxf(v[j].z - tau, 0.0f);
        float cw = fmaxf(v[j].w - tau, 0.0f);
        float4 p;
        p.x = cx * cx * inv;
        p.y = cy * cy * inv;
        p.z = cz * cz * inv;
        p.w = cw * cw * inv;
        dst[j * 32 + lane] = p;
    }
}

extern "C" void kernel_launch(void* const* d_in, const int* in_sizes, int n_in,
                              void* d_out, int out_size) {
    const float* X = (const float*)d_in[0];
    float* O = (float*)d_out;
    const int nrows = in_sizes[0] / D;                 // 65536
    const int grid = (nrows + WPB - 1) / WPB;
    normmax_active_kernel<<<grid, THREADS>>>(X, O, nrows);
}

// round 7
// speedup vs baseline: 1.1087x; 1.1044x over previous
#include <cuda_runtime.h>

// NormmaxBisect, alpha=1.5, d=2048: p = clamp(x - tau, 0)^2 / sum(...),
// tau solves sum(clamp(x - tau, 0)^3) = 1.
//
// One warp per row, row parked in SHARED memory (not registers) to lift
// occupancy to 24 warps/SM. Solver runs on a per-lane register active set
// (only x > rowmax-1 can ever contribute): 9 bisection + 3 Newton passes.
// Rare rows where some lane holds > DEPTH actives take a full-row smem solve.

#define D 2048
#define WARPS 4
#define THREADS (WARPS * 32)
#define DEPTH 8
#define NB_MAIN 9
#define NB_FB 20
#define NN 3
#define DM0 0.9779029130879204f   // 1 - (1/2048)^0.5

static __device__ __forceinline__ float warp_sum(float v) {
    #pragma unroll
    for (int o = 16; o; o >>= 1) v += __shfl_xor_sync(0xffffffffu, v, o);
    return v;
}
static __device__ __forceinline__ float warp_max(float v) {
    #pragma unroll
    for (int o = 16; o; o >>= 1) v = fmaxf(v, __shfl_xor_sync(0xffffffffu, v, o));
    return v;
}

// full-row sums from the smem row (fallback path)
static __device__ __forceinline__ float s3_row(const float4* r, int lane, float tau) {
    float s3 = 0.0f;
    #pragma unroll
    for (int j = 0; j < 16; ++j) {
        float4 t = r[j * 32 + lane];
        float cx = fmaxf(t.x - tau, 0.0f), cy = fmaxf(t.y - tau, 0.0f);
        float cz = fmaxf(t.z - tau, 0.0f), cw = fmaxf(t.w - tau, 0.0f);
        s3 = fmaf(cx * cx, cx, s3); s3 = fmaf(cy * cy, cy, s3);
        s3 = fmaf(cz * cz, cz, s3); s3 = fmaf(cw * cw, cw, s3);
    }
    return warp_sum(s3);
}
static __device__ __forceinline__ void s23_row(const float4* r, int lane, float tau,
                                               float& s2o, float& s3o) {
    float s2 = 0.0f, s3 = 0.0f;
    #pragma unroll
    for (int j = 0; j < 16; ++j) {
        float4 t = r[j * 32 + lane];
        float cx = fmaxf(t.x - tau, 0.0f), cy = fmaxf(t.y - tau, 0.0f);
        float cz = fmaxf(t.z - tau, 0.0f), cw = fmaxf(t.w - tau, 0.0f);
        float c2x = cx * cx, c2y = cy * cy, c2z = cz * cz, c2w = cw * cw;
        s2 += c2x + c2y + c2z + c2w;
        s3 = fmaf(c2x, cx, s3); s3 = fmaf(c2y, cy, s3);
        s3 = fmaf(c2z, cz, s3); s3 = fmaf(c2w, cw, s3);
    }
    s2o = warp_sum(s2);
    s3o = warp_sum(s3);
}

__global__ __launch_bounds__(THREADS, 6)
void normmax_smem_kernel(const float* __restrict__ X, float* __restrict__ O, int nrows) {
    __shared__ float4 srow[WARPS][D / 4];          // 32 KB
    __shared__ float  sact[WARPS][DEPTH][32];      //  4 KB
    const int w = blockIdx.x * WARPS + (threadIdx.x >> 5);
    if (w >= nrows) return;
    const int lane = threadIdx.x & 31;
    const int wl = threadIdx.x >> 5;
    float4* r = srow[wl];

    const float4* __restrict__ src = reinterpret_cast<const float4*>(X + (size_t)w * D);

    // ---- single DRAM read: load row -> smem, compute max in flight ----
    float mx = -3.4e38f;
    #pragma unroll
    for (int j = 0; j < 16; ++j) {
        float4 t = src[j * 32 + lane];
        r[j * 32 + lane] = t;
        mx = fmaxf(mx, fmaxf(fmaxf(t.x, t.y), fmaxf(t.z, t.w)));
    }
    mx = warp_max(mx);
    const float thr = mx - 1.0f;   // = tau_lo; only x > thr can contribute

    // ---- prefill active slots with sentinel (thr => zero contribution) ----
    #pragma unroll
    for (int k = 0; k < DEPTH; ++k) sact[wl][k][lane] = thr;

    // ---- per-lane compaction (order irrelevant; no cross-lane scan) ----
    int cnt = 0;
    #pragma unroll
    for (int j = 0; j < 16; ++j) {
        float4 t = r[j * 32 + lane];
        if (t.x > thr) { if (cnt < DEPTH) sact[wl][cnt][lane] = t.x; cnt++; }
        if (t.y > thr) { if (cnt < DEPTH) sact[wl][cnt][lane] = t.y; cnt++; }
        if (t.z > thr) { if (cnt < DEPTH) sact[wl][cnt][lane] = t.z; cnt++; }
        if (t.w > thr) { if (cnt < DEPTH) sact[wl][cnt][lane] = t.w; cnt++; }
    }
    const bool fb = __any_sync(0xffffffffu, cnt > DEPTH);

    float tau, s2;
    if (!fb) {
        // ---- register-resident active set ----
        float a[DEPTH];
        #pragma unroll
        for (int k = 0; k < DEPTH; ++k) a[k] = sact[wl][k][lane];

        float tau_lo = thr, dm = DM0;
        #pragma unroll
        for (int it = 0; it < NB_MAIN; ++it) {
            dm *= 0.5f;
            const float tm = tau_lo + dm;
            float s3 = 0.0f;
            #pragma unroll
            for (int k = 0; k < DEPTH; ++k) {
                float c = fmaxf(a[k] - tm, 0.0f);
                s3 = fmaf(c * c, c, s3);
            }
            s3 = warp_sum(s3);
            if (s3 >= 1.0f) tau_lo = tm;      // warp-uniform
        }
        tau = tau_lo;
        #pragma unroll
        for (int it = 0; it < NN; ++it) {
            float l2 = 0.0f, l3 = 0.0f;
            #pragma unroll
            for (int k = 0; k < DEPTH; ++k) {
                float c = fmaxf(a[k] - tau, 0.0f);
                float c2 = c * c;
                l2 += c2;
                l3 = fmaf(c2, c, l3);
            }
            const float rs2 = warp_sum(l2);
            const float rs3 = warp_sum(l3);
            tau += __fdividef(rs3 - 1.0f, 3.0f * rs2);   // convex, from f>=0 side
        }
        // normalization sum at final tau
        float l2 = 0.0f;
        #pragma unroll
        for (int k = 0; k < DEPTH; ++k) {
            float c = fmaxf(a[k] - tau, 0.0f);
            l2 = fmaf(c, c, l2);
        }
        s2 = warp_sum(l2);
    } else {
        // ---- rare fallback: full-row solve from smem ----
        float tau_lo = thr, dm = DM0;
        for (int it = 0; it < NB_FB; ++it) {
            dm *= 0.5f;
            const float tm = tau_lo + dm;
            if (s3_row(r, lane, tm) >= 1.0f) tau_lo = tm;
        }
        tau = tau_lo;
        for (int it = 0; it < NN; ++it) {
            float rs2, rs3;
            s23_row(r, lane, tau, rs2, rs3);
            tau += __fdividef(rs3 - 1.0f, 3.0f * rs2);
        }
        float dummy;
        s23_row(r, lane, tau, s2, dummy);
    }
    const float inv = __fdividef(1.0f, s2);

    // ---- output pass: read row from smem, write p ----
    float4* __restrict__ dst = reinterpret_cast<float4*>(O + (size_t)w * D);
    #pragma unroll
    for (int j = 0; j < 16; ++j) {
        float4 t = r[j * 32 + lane];
        float cx = fmaxf(t.x - tau, 0.0f), cy = fmaxf(t.y - tau, 0.0f);
        float cz = fmaxf(t.z - tau, 0.0f), cw = fmaxf(t.w - tau, 0.0f);
        float4 p;
        p.x = cx * cx * inv;
        p.y = cy * cy * inv;
        p.z = cz * cz * inv;
        p.w = cw * cw * inv;
        dst[j * 32 + lane] = p;
    }
}

extern "C" void kernel_launch(void* const* d_in, const int* in_sizes, int n_in,
                              void* d_out, int out_size) {
    const float* X = (const float*)d_in[0];
    float* O = (float*)d_out;
    const int nrows = in_sizes[0] / D;                 // 65536
    const int grid = (nrows + WARPS - 1) / WARPS;
    normmax_smem_kernel<<<grid, THREADS>>>(X, O, nrows);
}

// round 8
// speedup vs baseline: 1.4103x; 1.2721x over previous
#include <cuda_runtime.h>
#include <cstdint>

// NormmaxBisect, alpha=1.5, d=2048: p = clamp(x - tau, 0)^2 / sum(...),
// tau solves sum(clamp(x - tau, 0)^3) = 1.
//
// One warp per row, row in smem via cp.async. Only x > rowmax-1 can contribute
// to the solver sums; actives are compacted (deterministic prefix-scan order)
// into a per-warp smem list. Solver: 2 ballot-search rounds (33-way bracket
// split per round -> width 9e-4) + 3 Newton iterations computed redundantly by
// every lane (zero cross-lane traffic, warp-uniform tau). Rare rows with more
// than LISTCAP actives take a full-row warp-reduction solve.

#define D 2048
#define WARPS 4
#define THREADS (WARPS * 32)
#define LISTCAP 256
#define NROUNDS 2
#define NN 3
#define NB_FB 22
#define DM0 0.9779029130879204f   // 1 - (1/2048)^0.5

static __device__ __forceinline__ float warp_sum(float v) {
    #pragma unroll
    for (int o = 16; o; o >>= 1) v += __shfl_xor_sync(0xffffffffu, v, o);
    return v;
}
static __device__ __forceinline__ float warp_max(float v) {
    #pragma unroll
    for (int o = 16; o; o >>= 1) v = fmaxf(v, __shfl_xor_sync(0xffffffffu, v, o));
    return v;
}

// full-row sums from the smem row (fallback path only)
static __device__ __forceinline__ float s3_row(const float4* r, int lane, float tau) {
    float s3 = 0.0f;
    #pragma unroll
    for (int j = 0; j < 16; ++j) {
        float4 t = r[j * 32 + lane];
        float cx = fmaxf(t.x - tau, 0.0f), cy = fmaxf(t.y - tau, 0.0f);
        float cz = fmaxf(t.z - tau, 0.0f), cw = fmaxf(t.w - tau, 0.0f);
        s3 = fmaf(cx * cx, cx, s3); s3 = fmaf(cy * cy, cy, s3);
        s3 = fmaf(cz * cz, cz, s3); s3 = fmaf(cw * cw, cw, s3);
    }
    return warp_sum(s3);
}
static __device__ __forceinline__ void s23_row(const float4* r, int lane, float tau,
                                               float& s2o, float& s3o) {
    float s2 = 0.0f, s3 = 0.0f;
    #pragma unroll
    for (int j = 0; j < 16; ++j) {
        float4 t = r[j * 32 + lane];
        float cx = fmaxf(t.x - tau, 0.0f), cy = fmaxf(t.y - tau, 0.0f);
        float cz = fmaxf(t.z - tau, 0.0f), cw = fmaxf(t.w - tau, 0.0f);
        float c2x = cx * cx, c2y = cy * cy, c2z = cz * cz, c2w = cw * cw;
        s2 += c2x + c2y + c2z + c2w;
        s3 = fmaf(c2x, cx, s3); s3 = fmaf(c2y, cy, s3);
        s3 = fmaf(c2z, cz, s3); s3 = fmaf(c2w, cw, s3);
    }
    s2o = warp_sum(s2);
    s3o = warp_sum(s3);
}

__global__ __launch_bounds__(THREADS, 6)
void normmax_ballot_kernel(const float* __restrict__ X, float* __restrict__ O, int nrows) {
    __shared__ float4 srow[WARPS][D / 4];        // 32 KB
    __shared__ float  slist[WARPS][LISTCAP];     //  4 KB
    const int w = blockIdx.x * WARPS + (threadIdx.x >> 5);
    if (w >= nrows) return;
    const int lane = threadIdx.x & 31;
    const int wl = threadIdx.x >> 5;
    float4* r = srow[wl];
    float* lst = slist[wl];

    const float4* __restrict__ src = reinterpret_cast<const float4*>(X + (size_t)w * D);

    // ---- row -> smem via cp.async (full MLP, no register staging) ----
    #pragma unroll
    for (int j = 0; j < 16; ++j) {
        uint32_t sa = (uint32_t)__cvta_generic_to_shared(&r[j * 32 + lane]);
        asm volatile("cp.async.cg.shared.global [%0], [%1], 16;\n"
                     :: "r"(sa), "l"(src + j * 32 + lane));
    }
    asm volatile("cp.async.commit_group;\n");
    asm volatile("cp.async.wait_group 0;\n" ::: "memory");
    // each lane reads back only the slots it wrote -> no cross-lane sync needed yet

    // ---- warp max ----
    float mx = -3.4e38f;
    #pragma unroll
    for (int j = 0; j < 16; ++j) {
        float4 t = r[j * 32 + lane];
        mx = fmaxf(mx, fmaxf(fmaxf(t.x, t.y), fmaxf(t.z, t.w)));
    }
    mx = warp_max(mx);
    const float thr = mx - 1.0f;   // = tau_lo; only x > thr can ever contribute

    // ---- count actives per lane + prefix scan (deterministic order) ----
    int cnt = 0;
    #pragma unroll
    for (int j = 0; j < 16; ++j) {
        float4 t = r[j * 32 + lane];
        cnt += (t.x > thr) + (t.y > thr) + (t.z > thr) + (t.w > thr);
    }
    int pre = cnt;
    #pragma unroll
    for (int o = 1; o < 32; o <<= 1) {
        int t = __shfl_up_sync(0xffffffffu, pre, o);
        if (lane >= o) pre += t;
    }
    const int total = __shfl_sync(0xffffffffu, pre, 31);   // >= 1 always

    float tau, inv;
    if (total <= LISTCAP) {
        // ---- compact actives into the shared list ----
        int k = pre - cnt;
        #pragma unroll
        for (int j = 0; j < 16; ++j) {
            float4 t = r[j * 32 + lane];
            if (t.x > thr) lst[k++] = t.x;
            if (t.y > thr) lst[k++] = t.y;
            if (t.z > thr) lst[k++] = t.z;
            if (t.w > thr) lst[k++] = t.w;
        }
        __syncwarp();

        // ---- 2 ballot-search rounds: 33-way bracket split per round ----
        float lo = thr;          // f(lo) >= 1 - 1 >= 0 guaranteed
        float wd = DM0;
        #pragma unroll
        for (int rnd = 0; rnd < NROUNDS; ++rnd) {
            const float step = wd * (1.0f / 33.0f);
            const float tm = lo + step * (float)(lane + 1);
            float s3 = 0.0f;
            for (int i = 0; i < total; ++i) {            // LDS broadcast reads
                float c = fmaxf(lst[i] - tm, 0.0f);
                s3 = fmaf(c * c, c, s3);
            }
            const unsigned b = __ballot_sync(0xffffffffu, s3 >= 1.0f);
            const int m = 32 - __clz(b);   // # satisfying lanes (contiguous from 0)
            lo += step * (float)m;         // f(lo) still >= 0
            wd = step;
        }

        // ---- 3 Newton steps, computed redundantly by every lane ----
        tau = lo;
        #pragma unroll
        for (int it = 0; it < NN; ++it) {
            float s2 = 0.0f, s3 = 0.0f;
            for (int i = 0; i < total; ++i) {
                float c = fmaxf(lst[i] - tau, 0.0f);
                float c2 = c * c;
                s2 += c2;
                s3 = fmaf(c2, c, s3);
            }
            // f convex & decreasing; from f>=0 side Newton is monotone, s2 > 0
            tau += __fdividef(s3 - 1.0f, 3.0f * s2);
        }
        // ---- normalization sum at final tau ----
        float s2 = 0.0f;
        for (int i = 0; i < total; ++i) {
            float c = fmaxf(lst[i] - tau, 0.0f);
            s2 = fmaf(c, c, s2);
        }
        inv = __fdividef(1.0f, s2);
    } else {
        // ---- rare fallback: full-row solve with warp reductions ----
        float tau_lo = thr, dm = DM0;
        for (int it = 0; it < NB_FB; ++it) {
            dm *= 0.5f;
            const float tm = tau_lo + dm;
            if (s3_row(r, lane, tm) >= 1.0f) tau_lo = tm;
        }
        tau = tau_lo;
        for (int it = 0; it < NN; ++it) {
            float rs2, rs3;
            s23_row(r, lane, tau, rs2, rs3);
            tau += __fdividef(rs3 - 1.0f, 3.0f * rs2);
        }
        float s2, dummy;
        s23_row(r, lane, tau, s2, dummy);
        inv = __fdividef(1.0f, s2);
    }

    // ---- output pass: p = clamp(x - tau)^2 * inv ----
    float4* __restrict__ dst = reinterpret_cast<float4*>(O + (size_t)w * D);
    #pragma unroll
    for (int j = 0; j < 16; ++j) {
        float4 t = r[j * 32 + lane];
        float cx = fmaxf(t.x - tau, 0.0f), cy = fmaxf(t.y - tau, 0.0f);
        float cz = fmaxf(t.z - tau, 0.0f), cw = fmaxf(t.w - tau, 0.0f);
        float4 p;
        p.x = cx * cx * inv;
        p.y = cy * cy * inv;
        p.z = cz * cz * inv;
        p.w = cw * cw * inv;
        dst[j * 32 + lane] = p;
    }
}

extern "C" void kernel_launch(void* const* d_in, const int* in_sizes, int n_in,
                              void* d_out, int out_size) {
    const float* X = (const float*)d_in[0];
    float* O = (float*)d_out;
    const int nrows = in_sizes[0] / D;                 // 65536
    const int grid = (nrows + WARPS - 1) / WARPS;
    normmax_ballot_kernel<<<grid, THREADS>>>(X, O, nrows);
}